// round 4
// baseline (speedup 1.0000x reference)
#include <cuda_runtime.h>
#include <cstdint>

// Problem constants
#define Bsz   16
#define Jn    16
#define Cn    64
#define HW    65536            // 256*256 spatial
#define HW4   16384            // float4s per channel
#define NCH   (Bsz * Jn)       // 256 channels
#define NSEG  8                // segments per channel
#define TPB   256
#define SEGF4 (HW4 / NSEG)     // 2048 float4s per segment
#define PERT  (SEGF4 / TPB)    // 8 float4s per thread

// Device-global scratch (allocation-free; zero-init at load, reset by completers)
__device__ unsigned long long g_pack[NCH];  // (ordf(val)<<32) | (0xFFFFFFFF - idx)
__device__ int                g_cnt[NCH];   // segments done per channel
__device__ float              g_joint[NCH]; // per-(b,j) SSE over C
__device__ int                g_bcnt[Bsz];  // joints done per batch

__device__ __forceinline__ unsigned ordf(float f) {
    unsigned u = __float_as_uint(f);
    return (u & 0x80000000u) ? ~u : (u | 0x80000000u);
}

__global__ __launch_bounds__(TPB)
void fused_label_loss(const float* __restrict__ heatmap,
                      const float* __restrict__ pred,
                      const float* __restrict__ gt,
                      float* __restrict__ out)
{
    const int ch  = blockIdx.x >> 3;          // channel
    const int seg = blockIdx.x & (NSEG - 1);  // segment within channel
    const int tid = threadIdx.x;

    const float4* hm = reinterpret_cast<const float4*>(heatmap + (size_t)ch * HW);
    const int base = seg * SEGF4;

    // ---- branchless streaming max over this thread's 8 float4s ----
    float4 v[PERT];
    #pragma unroll
    for (int k = 0; k < PERT; ++k)
        v[k] = hm[base + tid + k * TPB];

    float bv = -3.402823466e+38f;
    int   bfi = base + tid;                   // winning float4 index (ascending scan
                                              // + strict '>' => first occurrence)
    #pragma unroll
    for (int k = 0; k < PERT; ++k) {
        float m01  = fmaxf(v[k].x, v[k].y);
        float m23  = fmaxf(v[k].z, v[k].w);
        float vmax = fmaxf(m01, m23);
        int   fi   = base + tid + k * TPB;
        bool  gt_  = vmax > bv;
        bv  = gt_ ? vmax : bv;
        bfi = gt_ ? fi   : bfi;
    }

    // recover exact element within winning float4 (L2 hit; heatmap fits in L2)
    float4 wv = hm[bfi];
    int e = 3;
    if (wv.z == bv) e = 2;
    if (wv.y == bv) e = 1;
    if (wv.x == bv) e = 0;
    int bi = bfi * 4 + e;

    // ---- block reduce (max value, lowest index on tie) ----
    __shared__ float sv[TPB];
    __shared__ int   si[TPB];
    __shared__ float s_warp[2];
    sv[tid] = bv; si[tid] = bi;
    __syncthreads();
    for (int s = TPB / 2; s > 0; s >>= 1) {
        if (tid < s) {
            float ov = sv[tid + s];
            int   oi = si[tid + s];
            if (ov > sv[tid] || (ov == sv[tid] && oi < si[tid])) {
                sv[tid] = ov; si[tid] = oi;
            }
        }
        __syncthreads();
    }

    // ---- publish + detect channel completion ----
    __shared__ int s_done, s_idx;
    if (tid == 0) {
        unsigned long long pk =
            ((unsigned long long)ordf(sv[0]) << 32) |
            (unsigned long long)(0xFFFFFFFFu - (unsigned)si[0]);
        atomicMax(&g_pack[ch], pk);
        __threadfence();
        int old = atomicAdd(&g_cnt[ch], 1);
        if (old == NSEG - 1) {
            __threadfence();
            unsigned long long fin = *(volatile unsigned long long*)&g_pack[ch];
            s_idx  = (int)(0xFFFFFFFFu - (unsigned)(fin & 0xFFFFFFFFull));
            s_done = 1;
            g_pack[ch] = 0;   // reset for next graph replay
            g_cnt[ch]  = 0;
        } else {
            s_done = 0;
        }
    }
    __syncthreads();

    // ---- completer: gather pred @ idx, MSE over C, then batch mean ----
    if (s_done) {
        const int idx = s_idx;
        const int b   = ch >> 4;
        if (tid < Cn) {
            float p = pred[((size_t)(b * Cn + tid)) * HW + idx];
            float g = gt[(size_t)ch * Cn + tid];
            float d = p - g;
            float acc = d * d;
            #pragma unroll
            for (int off = 16; off > 0; off >>= 1)
                acc += __shfl_xor_sync(0xFFFFFFFFu, acc, off);
            if ((tid & 31) == 0) s_warp[tid >> 5] = acc;
        }
        __syncthreads();
        if (tid == 0) {
            g_joint[ch] = s_warp[0] + s_warp[1];
            __threadfence();
            int ob = atomicAdd(&g_bcnt[b], 1);
            if (ob == Jn - 1) {
                g_bcnt[b] = 0;   // reset for next replay
                __threadfence();
                float tot = 0.f;
                #pragma unroll
                for (int jj = 0; jj < Jn; ++jj)
                    tot += *(volatile float*)&g_joint[b * Jn + jj];
                out[b] = tot * (1.0f / (float)(Jn * Cn));
            }
        }
    }
}

// ---------------------------------------------------------------------------
extern "C" void kernel_launch(void* const* d_in, const int* in_sizes, int n_in,
                              void* d_out, int out_size)
{
    const float* pred    = (const float*)d_in[0];  // [B,C,H,W]
    const float* gt      = (const float*)d_in[1];  // [B,J,C]
    const float* heatmap = (const float*)d_in[2];  // [B,J,H,W]
    float* out = (float*)d_out;                    // [B]

    fused_label_loss<<<NCH * NSEG, TPB>>>(heatmap, pred, gt, out);
}

// round 5
// speedup vs baseline: 1.3611x; 1.3611x over previous
#include <cuda_runtime.h>
#include <cstdint>

// Problem constants
#define Bsz 16
#define Jn  16
#define Cn  64
#define HW  65536              // 256*256
#define HW4 16384              // float4s per channel
#define NCH (Bsz * Jn)         // 256 channels = 256 CTAs
#define TPB 256
#define BATCH 8                // front-batched float4 loads per iteration
#define NITER (HW4 / (TPB * BATCH))   // 8 iterations

// Scratch for argmax indices (no device allocation allowed)
__device__ int g_argmax[NCH];

// ---------------------------------------------------------------------------
// Kernel A: per-(b,j) argmax over heatmap[b,j,:,:] (first-max-index semantics)
// One CTA per channel; branchless fmax-tree; 8-deep front-batched loads.
// ---------------------------------------------------------------------------
__global__ void argmax_kernel(const float* __restrict__ heatmap)
{
    const int ch  = blockIdx.x;
    const int tid = threadIdx.x;

    const float4* __restrict__ hm =
        reinterpret_cast<const float4*>(heatmap + (size_t)ch * HW);

    float bv  = -3.402823466e+38f;
    int   bfi = tid;                      // winning float4 index

    #pragma unroll
    for (int it = 0; it < NITER; ++it) {
        const int i0 = it * (TPB * BATCH) + tid;

        float4 v[BATCH];
        #pragma unroll
        for (int k = 0; k < BATCH; ++k)   // 8 independent LDG.128, front-batched
            v[k] = hm[i0 + k * TPB];

        #pragma unroll
        for (int k = 0; k < BATCH; ++k) {
            float m01  = fmaxf(v[k].x, v[k].y);
            float m23  = fmaxf(v[k].z, v[k].w);
            float vmax = fmaxf(m01, m23);
            int   fi   = i0 + k * TPB;
            // ascending fi + strict '>' => first occurrence within this thread
            if (vmax > bv) { bv = vmax; bfi = fi; }
        }
    }

    // Recover exact element within winning float4 (re-load; L2 hit).
    // Check descending so the LOWEST matching element index wins.
    float4 wv = hm[bfi];
    int e = 3;
    if (wv.z == bv) e = 2;
    if (wv.y == bv) e = 1;
    if (wv.x == bv) e = 0;
    int bi = bfi * 4 + e;

    // ---- block reduce: larger value wins, lower index on ties ----
    __shared__ float sv[TPB];
    __shared__ int   si[TPB];
    sv[tid] = bv; si[tid] = bi;
    __syncthreads();

    for (int s = TPB / 2; s > 0; s >>= 1) {
        if (tid < s) {
            float ov = sv[tid + s];
            int   oi = si[tid + s];
            if (ov > sv[tid] || (ov == sv[tid] && oi < si[tid])) {
                sv[tid] = ov; si[tid] = oi;
            }
        }
        __syncthreads();
    }

    if (tid == 0) g_argmax[ch] = si[0];
}

// ---------------------------------------------------------------------------
// Kernel B: gather pred at argmax, per-(b,j) MSE over C, mean over J.
// (identical to R1's measured version)
// ---------------------------------------------------------------------------
__global__ __launch_bounds__(512, 1)
void gather_mse_kernel(const float* __restrict__ pred,
                       const float* __restrict__ gt,
                       float* __restrict__ out)
{
    const int b    = blockIdx.x;
    const int tid  = threadIdx.x;
    const int warp = tid >> 5;     // joint
    const int lane = tid & 31;

    const int idx = g_argmax[b * Jn + warp];

    const float* predb = pred + (size_t)b * Cn * HW;
    const float* gtbj  = gt + ((size_t)b * Jn + warp) * Cn;

    float acc = 0.f;
    #pragma unroll
    for (int k = 0; k < 2; ++k) {
        int c = lane + 32 * k;
        float p = predb[(size_t)c * HW + idx];
        float d = p - gtbj[c];
        acc += d * d;
    }

    #pragma unroll
    for (int off = 16; off > 0; off >>= 1)
        acc += __shfl_xor_sync(0xFFFFFFFFu, acc, off);

    __shared__ float sj[Jn];
    if (lane == 0) sj[warp] = acc;
    __syncthreads();

    if (tid == 0) {
        float total = 0.f;
        #pragma unroll
        for (int j = 0; j < Jn; ++j) total += sj[j];
        out[b] = total / (float)(Jn * Cn);
    }
}

// ---------------------------------------------------------------------------
extern "C" void kernel_launch(void* const* d_in, const int* in_sizes, int n_in,
                              void* d_out, int out_size)
{
    const float* pred    = (const float*)d_in[0];  // [B,C,H,W]
    const float* gt      = (const float*)d_in[1];  // [B,J,C]
    const float* heatmap = (const float*)d_in[2];  // [B,J,H,W]
    float* out = (float*)d_out;                    // [B]

    argmax_kernel<<<NCH, TPB>>>(heatmap);
    gather_mse_kernel<<<Bsz, 512>>>(pred, gt, out);
}

// round 6
// speedup vs baseline: 1.5551x; 1.1425x over previous
#include <cuda_runtime.h>
#include <cstdint>

// Problem constants
#define Bsz 16
#define Jn  16
#define Cn  64
#define HW  65536              // 256*256
#define HW4 16384              // float4s per channel
#define NCH (Bsz * Jn)         // 256 channels = 256 CTAs
#define TPB 256
#define BATCH 8                // front-batched float4 loads per iteration
#define NITER (HW4 / (TPB * BATCH))   // 8 iterations

// Device-global scratch (allocation-free)
__device__ float g_joint[NCH];   // per-(b,j) sum of squared errors over C

// ---------------------------------------------------------------------------
// Kernel A: per-(b,j) argmax over heatmap[b,j,:,:] + fused pred gather & MSE.
// One CTA per channel; branchless fmax-tree; 8-deep front-batched loads.
// ---------------------------------------------------------------------------
__global__ void argmax_mse_kernel(const float* __restrict__ heatmap,
                                  const float* __restrict__ pred,
                                  const float* __restrict__ gt)
{
    const int ch  = blockIdx.x;
    const int tid = threadIdx.x;

    const float4* __restrict__ hm =
        reinterpret_cast<const float4*>(heatmap + (size_t)ch * HW);

    float bv  = -3.402823466e+38f;
    int   bfi = tid;                      // winning float4 index

    #pragma unroll
    for (int it = 0; it < NITER; ++it) {
        const int i0 = it * (TPB * BATCH) + tid;

        float4 v[BATCH];
        #pragma unroll
        for (int k = 0; k < BATCH; ++k)   // 8 independent LDG.128, front-batched
            v[k] = hm[i0 + k * TPB];

        #pragma unroll
        for (int k = 0; k < BATCH; ++k) {
            float m01  = fmaxf(v[k].x, v[k].y);
            float m23  = fmaxf(v[k].z, v[k].w);
            float vmax = fmaxf(m01, m23);
            int   fi   = i0 + k * TPB;
            // ascending fi + strict '>' => first occurrence within this thread
            if (vmax > bv) { bv = vmax; bfi = fi; }
        }
    }

    // Recover exact element within winning float4 (re-load; L2 hit).
    // Check descending so the LOWEST matching element index wins.
    float4 wv = hm[bfi];
    int e = 3;
    if (wv.z == bv) e = 2;
    if (wv.y == bv) e = 1;
    if (wv.x == bv) e = 0;
    int bi = bfi * 4 + e;

    // ---- block reduce: larger value wins, lower index on ties ----
    __shared__ float sv[TPB];
    __shared__ int   si[TPB];
    __shared__ float s_warp[2];
    sv[tid] = bv; si[tid] = bi;
    __syncthreads();

    for (int s = TPB / 2; s > 0; s >>= 1) {
        if (tid < s) {
            float ov = sv[tid + s];
            int   oi = si[tid + s];
            if (ov > sv[tid] || (ov == sv[tid] && oi < si[tid])) {
                sv[tid] = ov; si[tid] = oi;
            }
        }
        __syncthreads();
    }

    // ---- fused tail: gather pred @ argmax, squared error over C ----
    const int idx = si[0];
    const int b   = ch >> 4;              // ch / Jn

    if (tid < Cn) {
        float p = pred[((size_t)(b * Cn + tid)) * HW + idx];
        float g = gt[(size_t)ch * Cn + tid];     // (b*Jn+j)*Cn == ch*Cn
        float d = p - g;
        float acc = d * d;
        #pragma unroll
        for (int off = 16; off > 0; off >>= 1)
            acc += __shfl_xor_sync(0xFFFFFFFFu, acc, off);
        if ((tid & 31) == 0) s_warp[tid >> 5] = acc;
    }
    __syncthreads();

    if (tid == 0) g_joint[ch] = s_warp[0] + s_warp[1];
}

// ---------------------------------------------------------------------------
// Kernel B (trivial): per-batch mean over joints. One warp; lane b sums its
// 16 joints in fixed order (deterministic) and writes out[b].
// ---------------------------------------------------------------------------
__global__ void batch_mean_kernel(float* __restrict__ out)
{
    const int b = threadIdx.x;
    if (b < Bsz) {
        float tot = 0.f;
        #pragma unroll
        for (int j = 0; j < Jn; ++j)
            tot += g_joint[b * Jn + j];
        out[b] = tot * (1.0f / (float)(Jn * Cn));
    }
}

// ---------------------------------------------------------------------------
extern "C" void kernel_launch(void* const* d_in, const int* in_sizes, int n_in,
                              void* d_out, int out_size)
{
    const float* pred    = (const float*)d_in[0];  // [B,C,H,W]
    const float* gt      = (const float*)d_in[1];  // [B,J,C]
    const float* heatmap = (const float*)d_in[2];  // [B,J,H,W]
    float* out = (float*)d_out;                    // [B]

    argmax_mse_kernel<<<NCH, TPB>>>(heatmap, pred, gt);
    batch_mean_kernel<<<1, 32>>>(out);
}

// round 7
// speedup vs baseline: 1.8000x; 1.1575x over previous
#include <cuda_runtime.h>
#include <cstdint>

// Problem constants
#define Bsz 16
#define Jn  16
#define Cn  64
#define HW  65536              // 256*256
#define HW4 16384              // float4s per channel
#define NCH (Bsz * Jn)         // 256 channels = 256 CTAs
#define TPB 256
#define BATCH 8                // front-batched float4 loads per iteration
#define NITER (HW4 / (TPB * BATCH))   // 8 iterations

// Device-global scratch (allocation-free; zero-initialized at load)
__device__ float g_joint[NCH];   // per-(b,j) sum of squared errors over C
__device__ int   g_done;         // CTAs completed (reset by the elected CTA)

// ---------------------------------------------------------------------------
// Fused kernel: per-(b,j) argmax over heatmap + pred gather + MSE; the last
// CTA to finish computes the per-batch means and writes out[0..15].
// ---------------------------------------------------------------------------
__global__ void fused_label_loss(const float* __restrict__ heatmap,
                                 const float* __restrict__ pred,
                                 const float* __restrict__ gt,
                                 float* __restrict__ out)
{
    const int ch  = blockIdx.x;
    const int tid = threadIdx.x;

    const float4* __restrict__ hm =
        reinterpret_cast<const float4*>(heatmap + (size_t)ch * HW);

    float bv  = -3.402823466e+38f;
    int   bfi = tid;                      // winning float4 index

    #pragma unroll
    for (int it = 0; it < NITER; ++it) {
        const int i0 = it * (TPB * BATCH) + tid;

        float4 v[BATCH];
        #pragma unroll
        for (int k = 0; k < BATCH; ++k)   // 8 independent LDG.128, front-batched
            v[k] = hm[i0 + k * TPB];

        #pragma unroll
        for (int k = 0; k < BATCH; ++k) {
            float m01  = fmaxf(v[k].x, v[k].y);
            float m23  = fmaxf(v[k].z, v[k].w);
            float vmax = fmaxf(m01, m23);
            int   fi   = i0 + k * TPB;
            // ascending fi + strict '>' => first occurrence within this thread
            if (vmax > bv) { bv = vmax; bfi = fi; }
        }
    }

    // Recover exact element within winning float4 (re-load; L2 hit).
    // Check descending so the LOWEST matching element index wins.
    float4 wv = hm[bfi];
    int e = 3;
    if (wv.z == bv) e = 2;
    if (wv.y == bv) e = 1;
    if (wv.x == bv) e = 0;
    int bi = bfi * 4 + e;

    // ---- block reduce: larger value wins, lower index on ties ----
    __shared__ float sv[TPB];
    __shared__ int   si[TPB];
    __shared__ float s_warp[2];
    sv[tid] = bv; si[tid] = bi;
    __syncthreads();

    for (int s = TPB / 2; s > 0; s >>= 1) {
        if (tid < s) {
            float ov = sv[tid + s];
            int   oi = si[tid + s];
            if (ov > sv[tid] || (ov == sv[tid] && oi < si[tid])) {
                sv[tid] = ov; si[tid] = oi;
            }
        }
        __syncthreads();
    }

    // ---- fused tail: gather pred @ argmax, squared error over C ----
    const int idx = si[0];
    const int b   = ch >> 4;              // ch / Jn

    if (tid < Cn) {
        float p = pred[((size_t)(b * Cn + tid)) * HW + idx];
        float g = gt[(size_t)ch * Cn + tid];     // (b*Jn+j)*Cn == ch*Cn
        float d = p - g;
        float acc = d * d;
        #pragma unroll
        for (int off = 16; off > 0; off >>= 1)
            acc += __shfl_xor_sync(0xFFFFFFFFu, acc, off);
        if ((tid & 31) == 0) s_warp[tid >> 5] = acc;
    }
    __syncthreads();

    // ---- last-done CTA computes the per-batch means ----
    __shared__ int s_last;
    if (tid == 0) {
        g_joint[ch] = s_warp[0] + s_warp[1];
        __threadfence();                   // make g_joint[ch] globally visible
        int old = atomicAdd(&g_done, 1);
        s_last = (old == NCH - 1);
        if (s_last) g_done = 0;            // reset for next graph replay
    }
    __syncthreads();

    if (s_last && tid < Bsz) {
        __threadfence();                   // order: counter read -> g_joint reads
        float tot = 0.f;
        #pragma unroll
        for (int j = 0; j < Jn; ++j)       // fixed order -> deterministic
            tot += *(volatile float*)&g_joint[tid * Jn + j];
        out[tid] = tot * (1.0f / (float)(Jn * Cn));
    }
}

// ---------------------------------------------------------------------------
extern "C" void kernel_launch(void* const* d_in, const int* in_sizes, int n_in,
                              void* d_out, int out_size)
{
    const float* pred    = (const float*)d_in[0];  // [B,C,H,W]
    const float* gt      = (const float*)d_in[1];  // [B,J,C]
    const float* heatmap = (const float*)d_in[2];  // [B,J,H,W]
    float* out = (float*)d_out;                    // [B]

    fused_label_loss<<<NCH, TPB>>>(heatmap, pred, gt, out);
}